// round 5
// baseline (speedup 1.0000x reference)
#include <cuda_runtime.h>
#include <cuda_bf16.h>

// Align2D: bilinear warp (grid_sample, border padding) of x[8,64,512,512]
// by flow[8,2,512,512]. Output = concat(x_warp flattened, flow flattened).
//
// R5: per tap-row, one aligned LDG.128 window covering both horizontal taps
// (x0, x0+1), dotted with a precomputed 4-elem x-weight vector. Overflow
// element (x0%4==3, 25% of lanes) via predicated scalar load. Cuts gather
// L1 wavefronts ~40% vs 4 scalar taps. One pixel per thread (32-px warp
// footprint keeps per-instruction line count minimal).

#define BB 8
#define CC 64
#define HH 512
#define WW 512
#define HWP (HH * WW)

__global__ __launch_bounds__(256) void align2d_warp_kernel(
    const float* __restrict__ x,
    const float* __restrict__ flow,
    float* __restrict__ out)
{
    int pix = blockIdx.x * blockDim.x + threadIdx.x;
    if (pix >= BB * HWP) return;

    int b = pix >> 18;           // / HWP
    int p = pix & (HWP - 1);     // y*W + x
    int yi = p >> 9;
    int xi = p & (WW - 1);

    const float* fp = flow + (size_t)b * 2 * HWP + p;
    float fx = __ldg(fp);
    float fy = __ldg(fp + HWP);

    float px = fminf(fmaxf((float)xi + fx, 0.0f), (float)(WW - 1));
    float py = fminf(fmaxf((float)yi + fy, 0.0f), (float)(HH - 1));

    float x0f = floorf(px);
    float y0f = floorf(py);
    float wx = px - x0f;
    float wy = py - y0f;

    int x0 = (int)x0f;                 // in [0, W-1]
    int y0 = (int)y0f;
    int y1 = min(y0 + 1, HH - 1);

    // Aligned 4-wide window containing x0 (and x0+1 unless x0%4==3)
    int a      = x0 & 3;
    int wbase  = x0 & ~3;              // window start, %4 == 0, within row
    int i0     = (y0 << 9) + wbase;    // float4-aligned element index, row y0
    int i1     = (y1 << 9) + wbase;    // row y1
    bool need2 = (a == 3) && (x0 < WW - 1);
    int io0    = (y0 << 9) + x0 + 1;   // overflow elem (only read if need2)
    int io1    = (y1 << 9) + x0 + 1;

    // x-weight vector: xw[a] = 1-wx, xw[a+1] = wx (a<3); overflow carries wx
    float omwx = 1.0f - wx;
    float xw0 = (a == 0) ? omwx : 0.0f;
    float xw1 = (a == 1) ? omwx : ((a == 0) ? wx : 0.0f);
    float xw2 = (a == 2) ? omwx : ((a == 1) ? wx : 0.0f);
    float xw3 = (a == 3) ? omwx : ((a == 2) ? wx : 0.0f);
    float owx = need2 ? wx : 0.0f;

    float wyA = 1.0f - wy;
    float wyB = wy;

    const float* xb = x   + (size_t)b * CC * HWP;
    float*       ob = out + (size_t)b * CC * HWP + p;

    #pragma unroll 4
    for (int c = 0; c < CC; c++) {
        const float* xc = xb + (size_t)c * HWP;

        float4 f40 = __ldg((const float4*)(xc + i0));
        float4 f41 = __ldg((const float4*)(xc + i1));

        float va = 0.0f, vb = 0.0f;
        if (need2) {
            va = __ldg(xc + io0);
            vb = __ldg(xc + io1);
        }

        float t0 = fmaf(f40.x, xw0, fmaf(f40.y, xw1,
                   fmaf(f40.z, xw2, fmaf(f40.w, xw3, va * owx))));
        float t1 = fmaf(f41.x, xw0, fmaf(f41.y, xw1,
                   fmaf(f41.z, xw2, fmaf(f41.w, xw3, vb * owx))));

        ob[(size_t)c * HWP] = fmaf(t0, wyA, t1 * wyB);
    }
}

extern "C" void kernel_launch(void* const* d_in, const int* in_sizes, int n_in,
                              void* d_out, int out_size)
{
    const float* x    = (const float*)d_in[0];
    const float* flow = (const float*)d_in[1];
    float*       out  = (float*)d_out;

    int npix = BB * HWP;                    // 2,097,152
    int threads = 256;
    int blocks = (npix + threads - 1) / threads;
    align2d_warp_kernel<<<blocks, threads>>>(x, flow, out);

    // flow passthrough: second output component appended after warp output
    size_t warp_elems = (size_t)BB * CC * HWP;
    size_t flow_bytes = (size_t)BB * 2 * HWP * sizeof(float);
    cudaMemcpyAsync(out + warp_elems, flow, flow_bytes,
                    cudaMemcpyDeviceToDevice);
}

// round 9
// speedup vs baseline: 1.4404x; 1.4404x over previous
#include <cuda_runtime.h>
#include <cuda_bf16.h>

// Align2D: bilinear warp (grid_sample, border padding) of x[8,64,512,512]
// by flow[8,2,512,512]. Output = concat(x_warp flattened, flow flattened).
//
// R6: horizontal tap pair fused into one aligned LDG.64 at (x0 & ~1).
//  even x0: float2 = (v0, v1) directly.  odd x0: float2.y = v0, and v1
//  comes from a predicated scalar load (odd lanes only, ~50% active).
//  Cuts L1 wavefronts/channel-iter ~15 -> ~12.5 vs 4 scalar taps.
//  1 pixel/thread (keeps warp x-footprint at 32), unroll 8 for MLP.

#define BB 8
#define CC 64
#define HH 512
#define WW 512
#define HWP (HH * WW)

__global__ __launch_bounds__(256) void align2d_warp_kernel(
    const float* __restrict__ x,
    const float* __restrict__ flow,
    float* __restrict__ out)
{
    int pix = blockIdx.x * blockDim.x + threadIdx.x;
    if (pix >= BB * HWP) return;

    int b = pix >> 18;           // / HWP
    int p = pix & (HWP - 1);     // y*W + x
    int yi = p >> 9;
    int xi = p & (WW - 1);

    const float* fp = flow + (size_t)b * 2 * HWP + p;
    float fx = __ldg(fp);
    float fy = __ldg(fp + HWP);

    float px = fminf(fmaxf((float)xi + fx, 0.0f), (float)(WW - 1));
    float py = fminf(fmaxf((float)yi + fy, 0.0f), (float)(HH - 1));

    float x0f = floorf(px);
    float y0f = floorf(py);
    float wx = px - x0f;
    float wy = py - y0f;

    int x0 = (int)x0f;                 // in [0, W-1]
    int y0 = (int)y0f;
    int y1 = min(y0 + 1, HH - 1);

    bool odd = (x0 & 1) != 0;
    int  wb  = x0 & ~1;                // float2-aligned window start
    int  i0  = (y0 << 9) + wb;         // row y0 window index
    int  rd  = (y1 - y0) << 9;         // row delta (0 or 512)
    // overflow element x0+1 (only for odd lanes, and only if in-bounds)
    bool ovp = odd && (x0 < WW - 1);
    int  io0 = (y0 << 9) + x0 + 1;

    float omwx = 1.0f - wx;
    // window weights: even -> (1-wx, wx); odd -> (0, 1-wx) + overflow*wx
    float s0  = odd ? 0.0f : omwx;
    float s1  = odd ? omwx : wx;
    float sov = odd ? wx   : 0.0f;     // x0==511 odd => wx==0 => harmless

    float wyA = 1.0f - wy;
    float wyB = wy;

    const float* xb = x   + (size_t)b * CC * HWP;
    float*       ob = out + (size_t)b * CC * HWP + p;

    #pragma unroll 8
    for (int c = 0; c < CC; c++) {
        const float* xc = xb + (size_t)c * HWP;

        float2 a0 = __ldg((const float2*)(xc + i0));
        float2 a1 = __ldg((const float2*)(xc + i0 + rd));

        float o0 = 0.0f, o1 = 0.0f;
        if (ovp) {
            o0 = __ldg(xc + io0);
            o1 = __ldg(xc + io0 + rd);
        }

        float t0 = fmaf(a0.x, s0, fmaf(a0.y, s1, o0 * sov));
        float t1 = fmaf(a1.x, s0, fmaf(a1.y, s1, o1 * sov));

        ob[(size_t)c * HWP] = fmaf(t0, wyA, t1 * wyB);
    }
}

extern "C" void kernel_launch(void* const* d_in, const int* in_sizes, int n_in,
                              void* d_out, int out_size)
{
    const float* x    = (const float*)d_in[0];
    const float* flow = (const float*)d_in[1];
    float*       out  = (float*)d_out;

    int npix = BB * HWP;                    // 2,097,152
    int threads = 256;
    int blocks = (npix + threads - 1) / threads;
    align2d_warp_kernel<<<blocks, threads>>>(x, flow, out);

    // flow passthrough: second output component appended after warp output
    size_t warp_elems = (size_t)BB * CC * HWP;
    size_t flow_bytes = (size_t)BB * 2 * HWP * sizeof(float);
    cudaMemcpyAsync(out + warp_elems, flow, flow_bytes,
                    cudaMemcpyDeviceToDevice);
}

// round 10
// speedup vs baseline: 1.4474x; 1.0049x over previous
#include <cuda_runtime.h>
#include <cuda_bf16.h>

// Align2D: bilinear warp (grid_sample, border padding) of x[8,64,512,512]
// by flow[8,2,512,512]. Output = concat(x_warp flattened, flow flattened).
//
// R10 = R2 (best: scalar 4-tap gathers, lanes span consecutive x) with an
// occupancy push: __launch_bounds__(256, 8) forces regs <= 32 -> 64 warps/SM
// (R2 was reg-capped at 48 warps, L1 only 84% saturated). Batch via
// blockIdx.y removes the div + bounds check.

#define BB 8
#define CC 64
#define HH 512
#define WW 512
#define HWP (HH * WW)

__global__ __launch_bounds__(256, 8) void align2d_warp_kernel(
    const float* __restrict__ x,
    const float* __restrict__ flow,
    float* __restrict__ out)
{
    int p  = blockIdx.x * blockDim.x + threadIdx.x;  // y*W + x within image
    int b  = blockIdx.y;
    int yi = p >> 9;
    int xi = p & (WW - 1);

    const float* fp = flow + (size_t)b * 2 * HWP + p;
    float fx = __ldg(fp);
    float fy = __ldg(fp + HWP);

    float px = fminf(fmaxf((float)xi + fx, 0.0f), (float)(WW - 1));
    float py = fminf(fmaxf((float)yi + fy, 0.0f), (float)(HH - 1));

    float x0f = floorf(px);
    float y0f = floorf(py);
    float wx = px - x0f;
    float wy = py - y0f;

    int x0 = (int)x0f;                 // in [0, W-1] after clip
    int y0 = (int)y0f;
    int x1 = min(x0 + 1, WW - 1);
    int y1 = min(y0 + 1, HH - 1);

    int i00 = (y0 << 9) + x0;
    int i01 = (y0 << 9) + x1;
    int i10 = (y1 << 9) + x0;
    int i11 = (y1 << 9) + x1;

    float omwx = 1.0f - wx;
    float omwy = 1.0f - wy;
    float w00 = omwx * omwy;
    float w01 = wx * omwy;
    float w10 = omwx * wy;
    float w11 = wx * wy;

    const float* xc = x   + (size_t)b * CC * HWP;
    float*       ob = out + (size_t)b * CC * HWP + p;

    #pragma unroll 8
    for (int c = 0; c < CC; c++) {
        float v00 = __ldg(xc + i00);
        float v01 = __ldg(xc + i01);
        float v10 = __ldg(xc + i10);
        float v11 = __ldg(xc + i11);
        float v = fmaf(v00, w00, fmaf(v01, w01, fmaf(v10, w10, v11 * w11)));
        ob[(size_t)c * HWP] = v;
        xc += HWP;
    }
}

extern "C" void kernel_launch(void* const* d_in, const int* in_sizes, int n_in,
                              void* d_out, int out_size)
{
    const float* x    = (const float*)d_in[0];
    const float* flow = (const float*)d_in[1];
    float*       out  = (float*)d_out;

    dim3 grid(HWP / 256, BB);               // 1024 x 8 blocks
    align2d_warp_kernel<<<grid, 256>>>(x, flow, out);

    // flow passthrough: second output component appended after warp output
    size_t warp_elems = (size_t)BB * CC * HWP;
    size_t flow_bytes = (size_t)BB * 2 * HWP * sizeof(float);
    cudaMemcpyAsync(out + warp_elems, flow, flow_bytes,
                    cudaMemcpyDeviceToDevice);
}

// round 13
// speedup vs baseline: 1.6820x; 1.1620x over previous
#include <cuda_runtime.h>
#include <cuda_bf16.h>

// Align2D: bilinear warp (grid_sample, border padding) of x[8,64,512,512]
// by flow[8,2,512,512]. Output = concat(x_warp flattened, flow flattened).
//
// R11 = R2's winning scheme (scalar 4-tap gathers, 1 px/thread, unroll 8)
//  + launch_bounds(256,6): reg cap 42 keeps load batching, occ -> 75%
//  + flow passthrough fused into the kernel (fx,fy already in regs) --
//    removes the serial 33.6MB memcpy tail and 16.8MB of DRAM re-read.

#define BB 8
#define CC 64
#define HH 512
#define WW 512
#define HWP (HH * WW)

__global__ __launch_bounds__(256, 6) void align2d_warp_kernel(
    const float* __restrict__ x,
    const float* __restrict__ flow,
    float* __restrict__ out)
{
    int p  = blockIdx.x * blockDim.x + threadIdx.x;  // y*W + x within image
    int b  = blockIdx.y;
    int yi = p >> 9;
    int xi = p & (WW - 1);

    const float* fp = flow + (size_t)b * 2 * HWP + p;
    float fx = __ldg(fp);
    float fy = __ldg(fp + HWP);

    // flow passthrough (second output component, after warp output)
    float* of = out + (size_t)BB * CC * HWP + (size_t)b * 2 * HWP + p;
    of[0]   = fx;
    of[HWP] = fy;

    float px = fminf(fmaxf((float)xi + fx, 0.0f), (float)(WW - 1));
    float py = fminf(fmaxf((float)yi + fy, 0.0f), (float)(HH - 1));

    float x0f = floorf(px);
    float y0f = floorf(py);
    float wx = px - x0f;
    float wy = py - y0f;

    int x0 = (int)x0f;                 // in [0, W-1] after clip
    int y0 = (int)y0f;
    int x1 = min(x0 + 1, WW - 1);
    int y1 = min(y0 + 1, HH - 1);

    int i00 = (y0 << 9) + x0;
    int i01 = (y0 << 9) + x1;
    int i10 = (y1 << 9) + x0;
    int i11 = (y1 << 9) + x1;

    float omwx = 1.0f - wx;
    float omwy = 1.0f - wy;
    float w00 = omwx * omwy;
    float w01 = wx * omwy;
    float w10 = omwx * wy;
    float w11 = wx * wy;

    const float* xc = x   + (size_t)b * CC * HWP;
    float*       ob = out + (size_t)b * CC * HWP + p;

    #pragma unroll 8
    for (int c = 0; c < CC; c++) {
        float v00 = __ldg(xc + i00);
        float v01 = __ldg(xc + i01);
        float v10 = __ldg(xc + i10);
        float v11 = __ldg(xc + i11);
        float v = fmaf(v00, w00, fmaf(v01, w01, fmaf(v10, w10, v11 * w11)));
        ob[(size_t)c * HWP] = v;
        xc += HWP;
    }
}

extern "C" void kernel_launch(void* const* d_in, const int* in_sizes, int n_in,
                              void* d_out, int out_size)
{
    const float* x    = (const float*)d_in[0];
    const float* flow = (const float*)d_in[1];
    float*       out  = (float*)d_out;

    dim3 grid(HWP / 256, BB);               // 1024 x 8 blocks
    align2d_warp_kernel<<<grid, 256>>>(x, flow, out);
}